// round 3
// baseline (speedup 1.0000x reference)
#include <cuda_runtime.h>
#include <math.h>

// ---------------- problem constants ----------------
#define BB      16
#define NN      128
#define RR      16256
#define OBJD    64
#define RELD    32
#define EFFD    100
#define RHID    150
#define RIN     160      // 2*OBJD + RELD
#define OIN     164      // OBJD + EFFD
#define OHID    100

#define TILE_R  128
#define NTILES  127      // RR / TILE_R
#define KSPLIT  18

#define XS      164      // activation smem row stride (floats) -> (164%32)!=0, conflict-free row pairs
#define WS      160      // weight-stage row stride
#define SRS     132      // scatter R-tile row stride

// scratch (device globals: allocation-free per harness rules)
__device__ float g_effects[BB * RR * EFFD];                 // ~104 MB
__device__ float g_part[KSPLIT * BB * NN * EFFD];           // ~14.7 MB
__device__ float g_er[BB * NN * EFFD];                      // ~0.8 MB

// ---------------- fused relation-MLP layer ----------------
// A: smem [128, XS];  W: global [K, NOUT] row-major;  out: smem (stride XS) or global (stride NOUT)
template<int K, int NOUT, int NJ, bool TO_GLOBAL>
__device__ __forceinline__ void mlp_layer(
    const float* A, const float* __restrict__ W, const float* __restrict__ bias,
    float* Cs, float* Cg, float* sW, int tid, int tx, int ty)
{
    float acc[8][NJ];
#pragma unroll
    for (int i = 0; i < 8; i++)
#pragma unroll
        for (int j = 0; j < NJ; j++) acc[i][j] = 0.f;

    constexpr int KPAD = (K + 15) & ~15;
    for (int k0 = 0; k0 < KPAD; k0 += 16) {
        __syncthreads();
        for (int idx = tid; idx < 16 * WS; idx += 256) {
            int kk = idx / WS;
            int c  = idx - kk * WS;
            int k  = k0 + kk;
            sW[idx] = (k < K && c < NOUT) ? W[k * NOUT + c] : 0.f;
        }
        __syncthreads();
#pragma unroll
        for (int kk = 0; kk < 16; ++kk) {
            float a[8], w[NJ];
#pragma unroll
            for (int i = 0; i < 8; i++) a[i] = A[(ty + 16 * i) * XS + k0 + kk];
#pragma unroll
            for (int j = 0; j < NJ; j++) w[j] = sW[kk * WS + tx + 16 * j];
#pragma unroll
            for (int i = 0; i < 8; i++)
#pragma unroll
                for (int j = 0; j < NJ; j++) acc[i][j] = fmaf(a[i], w[j], acc[i][j]);
        }
    }
    if (TO_GLOBAL) {
#pragma unroll
        for (int i = 0; i < 8; i++) {
            int r = ty + 16 * i;
#pragma unroll
            for (int j = 0; j < NJ; j++) {
                int c = tx + 16 * j;
                if (c < NOUT) Cg[r * NOUT + c] = fmaxf(acc[i][j] + bias[c], 0.f);
            }
        }
    } else {
#pragma unroll
        for (int i = 0; i < 8; i++) {
            int r = ty + 16 * i;
#pragma unroll
            for (int j = 0; j < NJ; j++) {
                int c = tx + 16 * j;
                float v = 0.f;
                if (c < NOUT) v = fmaxf(acc[i][j] + bias[c], 0.f);
                Cs[r * XS + c] = v;   // pad cols [NOUT,160) zeroed for next layer's KPAD loop
            }
        }
    }
}

// ---------------- kernel A: gather + 4-layer relation MLP ----------------
// grid (NTILES, BB), 256 threads
__global__ __launch_bounds__(256, 1)
void gather_mlp_kernel(const float* __restrict__ objects,
                       const float* __restrict__ srel,
                       const float* __restrict__ rrel,
                       const float* __restrict__ relinfo,
                       const float* __restrict__ rw1, const float* __restrict__ rb1,
                       const float* __restrict__ rw2, const float* __restrict__ rb2,
                       const float* __restrict__ rw3, const float* __restrict__ rb3,
                       const float* __restrict__ rw4, const float* __restrict__ rb4)
{
    extern __shared__ float smem[];
    float* bufX = smem;                    // 128 x XS
    float* bufH = bufX + NN * XS;          // 128 x XS (also S/R staging at stride SRS)
    float* sAux = bufH + NN * XS;          // 8192 floats: O[128x64], later W stage [16x160]

    const int tid = threadIdx.x;
    const int tx = tid & 15, ty = tid >> 4;
    const int t = blockIdx.x, b = blockIdx.y;
    const int r0 = t * TILE_R;

    // objects[b] -> sAux  [n*64 + d]
    const float* Ob = objects + (size_t)b * NN * OBJD;
    for (int i = tid; i < NN * OBJD; i += 256) sAux[i] = Ob[i];

    // relation_info -> bufX[:, 128:160]
    const float* RI = relinfo + ((size_t)b * RR + r0) * RELD;
    for (int i = tid; i < TILE_R * RELD; i += 256) {
        int r = i >> 5, c = i & 31;
        bufX[r * XS + 128 + c] = RI[i];
    }

    // gather: senders (pass 0) -> bufX[:,0:64], receivers (pass 1) -> bufX[:,64:128]
    for (int pass = 0; pass < 2; ++pass) {
        const float* Rel = pass ? rrel : srel;
        __syncthreads();
        for (int i = tid; i < NN * TILE_R; i += 256) {
            int n = i >> 7, r = i & 127;
            bufH[n * SRS + r] = Rel[((size_t)b * NN + n) * RR + r0 + r];
        }
        __syncthreads();
        float acc[8][4];
#pragma unroll
        for (int i = 0; i < 8; i++)
#pragma unroll
            for (int j = 0; j < 4; j++) acc[i][j] = 0.f;
        for (int n = 0; n < NN; ++n) {
            float a[8], w[4];
#pragma unroll
            for (int i = 0; i < 8; i++) a[i] = bufH[n * SRS + ty + 16 * i];
#pragma unroll
            for (int j = 0; j < 4; j++) w[j] = sAux[n * OBJD + tx + 16 * j];
#pragma unroll
            for (int i = 0; i < 8; i++)
#pragma unroll
                for (int j = 0; j < 4; j++) acc[i][j] = fmaf(a[i], w[j], acc[i][j]);
        }
#pragma unroll
        for (int i = 0; i < 8; i++)
#pragma unroll
            for (int j = 0; j < 4; j++)
                bufX[(ty + 16 * i) * XS + pass * 64 + tx + 16 * j] = acc[i][j];
    }

    float* sW = sAux;   // overwrites O after first layer's internal barrier
    float* effp = g_effects + ((size_t)b * RR + r0) * EFFD;

    mlp_layer<RIN,  RHID, 10, false>(bufX, rw1, rb1, bufH, nullptr, sW, tid, tx, ty);
    mlp_layer<RHID, RHID, 10, false>(bufH, rw2, rb2, bufX, nullptr, sW, tid, tx, ty);
    mlp_layer<RHID, RHID, 10, false>(bufX, rw3, rb3, bufH, nullptr, sW, tid, tx, ty);
    mlp_layer<RHID, EFFD, 7,  true >(bufH, rw4, rb4, nullptr, effp, sW, tid, tx, ty);
}

// ---------------- kernel B: scatter (split-K, deterministic partials) ----------------
// grid (KSPLIT, BB), 256 threads
__global__ __launch_bounds__(256, 1)
void scatter_kernel(const float* __restrict__ rrel)
{
    extern __shared__ float smem[];
    float* sR = smem;            // 128 x SRS
    float* sE = sR + NN * SRS;   // 128 x EFFD
    const int tid = threadIdx.x, tx = tid & 15, ty = tid >> 4;
    const int split = blockIdx.x, b = blockIdx.y;

    float acc[8][7];
#pragma unroll
    for (int i = 0; i < 8; i++)
#pragma unroll
        for (int j = 0; j < 7; j++) acc[i][j] = 0.f;

    for (int t = split; t < NTILES; t += KSPLIT) {
        int r0 = t * TILE_R;
        __syncthreads();
        for (int i = tid; i < NN * TILE_R; i += 256) {
            int n = i >> 7, r = i & 127;
            sR[n * SRS + r] = rrel[((size_t)b * NN + n) * RR + r0 + r];
        }
        const float* E = g_effects + ((size_t)b * RR + r0) * EFFD;
        for (int i = tid; i < TILE_R * EFFD; i += 256) sE[i] = E[i];
        __syncthreads();
        for (int r = 0; r < TILE_R; ++r) {
            float a[8], w[7];
#pragma unroll
            for (int i = 0; i < 8; i++) a[i] = sR[(ty + 16 * i) * SRS + r];
#pragma unroll
            for (int j = 0; j < 7; j++) {
                int c = tx + 16 * j;
                w[j] = (c < EFFD) ? sE[r * EFFD + c] : 0.f;
            }
#pragma unroll
            for (int i = 0; i < 8; i++)
#pragma unroll
                for (int j = 0; j < 7; j++) acc[i][j] = fmaf(a[i], w[j], acc[i][j]);
        }
    }

    float* P = g_part + ((size_t)split * BB + b) * NN * EFFD;
#pragma unroll
    for (int i = 0; i < 8; i++) {
        int n = ty + 16 * i;
#pragma unroll
        for (int j = 0; j < 7; j++) {
            int c = tx + 16 * j;
            if (c < EFFD) P[n * EFFD + c] = acc[i][j];
        }
    }
}

// ---------------- kernel C: reduce split-K partials ----------------
__global__ void reduce_kernel()
{
    int i = blockIdx.x * blockDim.x + threadIdx.x;
    if (i < BB * NN * EFFD) {
        float s = 0.f;
#pragma unroll
        for (int k = 0; k < KSPLIT; ++k)
            s += g_part[(size_t)k * (BB * NN * EFFD) + i];
        g_er[i] = s;
    }
}

// ---------------- kernel D: final object MLP + sigmoid ----------------
// grid (BB*NN), 128 threads, one row per block
__global__ __launch_bounds__(128)
void final_kernel(const float* __restrict__ objects,
                  const float* __restrict__ ow1, const float* __restrict__ ob1,
                  const float* __restrict__ ow2, const float* __restrict__ ob2,
                  float* __restrict__ out)
{
    __shared__ float y[OIN];
    __shared__ float red[128];
    const int row = blockIdx.x;
    const int t = threadIdx.x;

    if (t < OBJD) y[t] = objects[(size_t)row * OBJD + t];
    if (t < EFFD) y[OBJD + t] = g_er[(size_t)row * EFFD + t];
    __syncthreads();

    float v = 0.f;
    if (t < OHID) {
        float acc = ob1[t];
#pragma unroll 4
        for (int k = 0; k < OIN; ++k) acc = fmaf(y[k], ow1[k * OHID + t], acc);
        v = fmaxf(acc, 0.f) * ow2[t];
    }
    red[t] = v;
    __syncthreads();
    for (int s = 64; s > 0; s >>= 1) {
        if (t < s) red[t] += red[t + s];
        __syncthreads();
    }
    if (t == 0) out[row] = 1.f / (1.f + expf(-(red[0] + ob2[0])));
}

// ---------------- launch ----------------
extern "C" void kernel_launch(void* const* d_in, const int* in_sizes, int n_in,
                              void* d_out, int out_size)
{
    const float* objects = (const float*)d_in[0];
    const float* srel    = (const float*)d_in[1];
    const float* rrel    = (const float*)d_in[2];
    const float* relinfo = (const float*)d_in[3];
    const float* rw1 = (const float*)d_in[4];
    const float* rb1 = (const float*)d_in[5];
    const float* rw2 = (const float*)d_in[6];
    const float* rb2 = (const float*)d_in[7];
    const float* rw3 = (const float*)d_in[8];
    const float* rb3 = (const float*)d_in[9];
    const float* rw4 = (const float*)d_in[10];
    const float* rb4 = (const float*)d_in[11];
    const float* ow1 = (const float*)d_in[12];
    const float* ob1 = (const float*)d_in[13];
    const float* ow2 = (const float*)d_in[14];
    const float* ob2 = (const float*)d_in[15];
    float* out = (float*)d_out;

    const int GATHER_SMEM  = (2 * NN * XS + 8192) * (int)sizeof(float);   // 200704 B
    const int SCATTER_SMEM = (NN * SRS + NN * EFFD) * (int)sizeof(float); // 118784 B

    cudaFuncSetAttribute(gather_mlp_kernel, cudaFuncAttributeMaxDynamicSharedMemorySize, GATHER_SMEM);
    cudaFuncSetAttribute(scatter_kernel,   cudaFuncAttributeMaxDynamicSharedMemorySize, SCATTER_SMEM);

    gather_mlp_kernel<<<dim3(NTILES, BB), 256, GATHER_SMEM>>>(
        objects, srel, rrel, relinfo,
        rw1, rb1, rw2, rb2, rw3, rb3, rw4, rb4);

    scatter_kernel<<<dim3(KSPLIT, BB), 256, SCATTER_SMEM>>>(rrel);

    reduce_kernel<<<(BB * NN * EFFD + 255) / 256, 256>>>();

    final_kernel<<<BB * NN, 128>>>(objects, ow1, ob1, ow2, ob2, out);
}

// round 8
// speedup vs baseline: 1.3709x; 1.3709x over previous
#include <cuda_runtime.h>
#include <math.h>
#include <cstdint>

// ---------------- problem constants ----------------
#define BB      16
#define NN      128
#define RR      16256
#define OBJD    64
#define RELD    32
#define EFFD    100
#define RHID    150
#define RIN     160      // 2*OBJD + RELD
#define OIN     164      // OBJD + EFFD
#define OHID    100

#define TILE_R  128
#define NTILES  127      // RR / TILE_R
#define KSPLIT  18

// smem strides (floats), conflict-free for the PTX m16n8k8.tf32 fragment patterns:
//  A-operand (scalar ld at row*S + c and +4): S % 32 == 4 -> bank (4g+c) bijective
//  B-operand (scalar ld at c*S + g): S % 32 in {8,24} -> bank (8c+g)/(24c+g) bijective
#define XS      164      // activations (A), 164%32=4
#define OTS     132      // O^T (A, gather), 132%32=4
#define SRS     132      // rel tile (A, scatter), 132%32=4
#define RTS     136      // rel tile (B, gather), 136%32=8
#define WST     152      // weight stage (B, MLP), 152%32=24
#define EST     104      // effects tile (B, scatter), 104%32=8

#define KCH     40       // weight-stage K chunk (multiple of 8)

// scratch (device globals: allocation-free per harness rules)
__device__ float g_effects[BB * RR * EFFD];                 // ~104 MB
__device__ float g_part[KSPLIT * BB * NN * EFFD];           // ~14.7 MB
__device__ float g_er[BB * NN * EFFD];                      // ~0.8 MB

// ---------------- tf32 split helpers ----------------
// x = hi + lo, each tf32-representable; aH*bH + aL*bH + aH*bL ~ 22-bit product.
__device__ __forceinline__ void split_tf32(float x, uint32_t& h, uint32_t& l) {
    asm("cvt.rna.tf32.f32 %0, %1;" : "=r"(h) : "f"(x));
    float r = x - __uint_as_float(h);      // exact (Sterbenz-like, hi has >= as many bits)
    asm("cvt.rna.tf32.f32 %0, %1;" : "=r"(l) : "f"(r));
}

// D += A(16x8,row) * B(8x8,col)  (tf32 inputs, f32 accum)
// PTX layout: a0=(g,c) a1=(g+8,c) a2=(g,c+4) a3=(g+8,c+4); b0=(c,g) b1=(c+4,g)
// C: c0=(g,2c) c1=(g,2c+1) c2=(g+8,2c) c3=(g+8,2c+1)
__device__ __forceinline__ void mma_tf32(float acc[4], const uint32_t a[4],
                                         uint32_t b0, uint32_t b1) {
    asm volatile(
        "mma.sync.aligned.m16n8k8.row.col.f32.tf32.tf32.f32 "
        "{%0,%1,%2,%3}, {%4,%5,%6,%7}, {%8,%9}, {%0,%1,%2,%3};\n"
        : "+f"(acc[0]), "+f"(acc[1]), "+f"(acc[2]), "+f"(acc[3])
        : "r"(a[0]), "r"(a[1]), "r"(a[2]), "r"(a[3]), "r"(b0), "r"(b1));
}

// load + split the A fragment: rows {row,row+8}, k-cols {kbase+c, kbase+c+4}
__device__ __forceinline__ void load_a_frag(const float* A, int row, int stride,
                                            int kbase, int c,
                                            uint32_t ah[4], uint32_t al[4]) {
    const float* Ap = A + row * stride + kbase + c;
    float x0 = Ap[0];            // (row,   c)
    float x1 = Ap[8 * stride];   // (row+8, c)
    float x2 = Ap[4];            // (row,   c+4)
    float x3 = Ap[8 * stride + 4]; // (row+8, c+4)
    split_tf32(x0, ah[0], al[0]);
    split_tf32(x1, ah[1], al[1]);
    split_tf32(x2, ah[2], al[2]);
    split_tf32(x3, ah[3], al[3]);
}

// ---------------- fused relation-MLP layer (3xTF32 tensor-core) ----------------
// A: smem [128, XS] raw fp32. W: global [K, NOUT] fp32 (pre-split to sWh/sWl).
// Output relu(A@W+b): Cs smem raw fp32 (zero-pads cols [NOUT, NT*8)) or Cg global.
template<int K, int NOUT, bool TO_GLOBAL>
__device__ __forceinline__ void mlp_layer_mma(
    const float* A, const float* __restrict__ W, const float* __restrict__ bias,
    float* Cs, float* Cg, float* sWh, float* sWl, int tid)
{
    constexpr int NT   = (NOUT + 7) / 8;
    constexpr int KPAD = (K + 7) & ~7;
    const int lane = tid & 31, warp = tid >> 5;
    const int g = lane >> 2, c = lane & 3;
    const int row = warp * 16 + g;

    float acc[NT][4];
#pragma unroll
    for (int nt = 0; nt < NT; nt++)
#pragma unroll
        for (int q = 0; q < 4; q++) acc[nt][q] = 0.f;

    for (int k0 = 0; k0 < KPAD; k0 += KCH) {
        const int rows = (KPAD - k0) < KCH ? (KPAD - k0) : KCH;
        __syncthreads();
        for (int idx = tid; idx < rows * WST; idx += 256) {
            int kk = idx / WST, cc = idx - kk * WST;
            int k = k0 + kk;
            float v = (k < K && cc < NOUT) ? W[k * NOUT + cc] : 0.f;
            uint32_t h, l;
            split_tf32(v, h, l);
            sWh[idx] = __uint_as_float(h);
            sWl[idx] = __uint_as_float(l);
        }
        __syncthreads();
        for (int ks = 0; ks < rows; ks += 8) {
            uint32_t ah[4], al[4];
            load_a_frag(A, row, XS, k0 + ks, c, ah, al);
            const float* Bh = sWh + (ks + c) * WST + g;
            const float* Bl = sWl + (ks + c) * WST + g;
#pragma unroll
            for (int nt = 0; nt < NT; nt++) {
                uint32_t bh0 = __float_as_uint(Bh[nt * 8]);
                uint32_t bh1 = __float_as_uint(Bh[4 * WST + nt * 8]);
                uint32_t bl0 = __float_as_uint(Bl[nt * 8]);
                uint32_t bl1 = __float_as_uint(Bl[4 * WST + nt * 8]);
                mma_tf32(acc[nt], al, bh0, bh1);
                mma_tf32(acc[nt], ah, bl0, bl1);
                mma_tf32(acc[nt], ah, bh0, bh1);
            }
        }
    }

    // C layout: c0 (row,2c) c1 (row,2c+1) c2 (row+8,2c) c3 (row+8,2c+1)
#pragma unroll
    for (int nt = 0; nt < NT; nt++) {
#pragma unroll
        for (int q = 0; q < 4; q++) {
            int col = nt * 8 + 2 * c + (q & 1);
            int r   = row + ((q & 2) ? 8 : 0);
            if (TO_GLOBAL) {
                if (col < NOUT)
                    Cg[r * NOUT + col] = fmaxf(acc[nt][q] + __ldg(&bias[col]), 0.f);
            } else {
                float o = (col < NOUT) ? fmaxf(acc[nt][q] + __ldg(&bias[col]), 0.f) : 0.f;
                Cs[r * XS + col] = o;
            }
        }
    }
}

// ---------------- kernel A: gather + 4-layer relation MLP ----------------
// grid (NTILES, BB), 256 threads
__global__ __launch_bounds__(256, 1)
void gather_mlp_kernel(const float* __restrict__ objects,
                       const float* __restrict__ srel,
                       const float* __restrict__ rrel,
                       const float* __restrict__ relinfo,
                       const float* __restrict__ rw1, const float* __restrict__ rb1,
                       const float* __restrict__ rw2, const float* __restrict__ rb2,
                       const float* __restrict__ rw3, const float* __restrict__ rb3,
                       const float* __restrict__ rw4, const float* __restrict__ rb4)
{
    extern __shared__ float smem[];
    float* bufX = smem;                    // 128 x XS (raw fp32 activations)
    float* bufH = bufX + NN * XS;          // 128 x XS; during gather holds rel tile [128 x RTS]
    float* sAux = bufH + NN * XS;          // max(64*OTS, 2*KCH*WST) floats

    const int tid  = threadIdx.x;
    const int lane = tid & 31, warp = tid >> 5;
    const int g = lane >> 2, c = lane & 3;
    const int t = blockIdx.x, b = blockIdx.y;
    const int r0 = t * TILE_R;

    // stage O^T (raw fp32): sAux[d*OTS + n] = O[n][d]
    const float* Ob = objects + (size_t)b * NN * OBJD;
    for (int i = tid; i < NN * OBJD; i += 256) {
        int n = i >> 6, d = i & 63;
        sAux[d * OTS + n] = Ob[i];
    }

    // relation_info -> bufX[:, 128:160] (raw fp32)
    const float* RI = relinfo + ((size_t)b * RR + r0) * RELD;
    for (int i = tid; i < TILE_R * RELD; i += 256) {
        int r = i >> 5, cc = i & 31;
        bufX[r * XS + 128 + cc] = RI[i];
    }

    // gather via mma: D[d][r] = sum_n O^T[d][n] * Rel[n][r]
    const int mw = warp & 3;     // d-tile (4 x 16 rows = 64)
    const int rh = warp >> 2;    // r-half (2 x 64 cols)
    for (int pass = 0; pass < 2; ++pass) {
        const float* Rel = pass ? rrel : srel;
        __syncthreads();
        for (int i = tid; i < NN * TILE_R; i += 256) {
            int n = i >> 7, r = i & 127;
            bufH[n * RTS + r] = Rel[((size_t)b * NN + n) * RR + r0 + r];
        }
        __syncthreads();

        float acc[8][4];
#pragma unroll
        for (int nt = 0; nt < 8; nt++)
#pragma unroll
            for (int q = 0; q < 4; q++) acc[nt][q] = 0.f;

        for (int ks = 0; ks < NN; ks += 8) {
            uint32_t ah[4], al[4];
            load_a_frag(sAux, mw * 16 + g, OTS, ks, c, ah, al);
            const float* Bp = bufH + (ks + c) * RTS + rh * 64 + g;
#pragma unroll
            for (int nt = 0; nt < 8; nt++) {
                uint32_t bh0, bl0, bh1, bl1;
                split_tf32(Bp[nt * 8], bh0, bl0);
                split_tf32(Bp[4 * RTS + nt * 8], bh1, bl1);
                mma_tf32(acc[nt], al, bh0, bh1);
                mma_tf32(acc[nt], ah, bl0, bl1);
                mma_tf32(acc[nt], ah, bh0, bh1);
            }
        }
        // D[d][r] -> bufX[r*XS + pass*64 + d]  (raw fp32)
#pragma unroll
        for (int nt = 0; nt < 8; nt++) {
#pragma unroll
            for (int q = 0; q < 4; q++) {
                int d = mw * 16 + g + ((q & 2) ? 8 : 0);
                int r = rh * 64 + nt * 8 + 2 * c + (q & 1);
                bufX[r * XS + pass * 64 + d] = acc[nt][q];
            }
        }
    }

    float* sWh = sAux;              // O^T dead after gather (sync inside layer)
    float* sWl = sAux + KCH * WST;
    float* effp = g_effects + ((size_t)b * RR + r0) * EFFD;

    mlp_layer_mma<RIN,  RHID, false>(bufX, rw1, rb1, bufH, nullptr, sWh, sWl, tid);
    mlp_layer_mma<RHID, RHID, false>(bufH, rw2, rb2, bufX, nullptr, sWh, sWl, tid);
    mlp_layer_mma<RHID, RHID, false>(bufX, rw3, rb3, bufH, nullptr, sWh, sWl, tid);
    mlp_layer_mma<RHID, EFFD, true >(bufH, rw4, rb4, nullptr, effp, sWh, sWl, tid);
}

// ---------------- kernel B: scatter (split-K, 3xTF32, deterministic) ----------------
// grid (KSPLIT, BB), 256 threads.  D[n][e] = sum_r Rel[n][r] * E[r][e]
__global__ __launch_bounds__(256, 1)
void scatter_kernel(const float* __restrict__ rrel)
{
    extern __shared__ float smem[];
    float* sR  = smem;                 // 128 x SRS raw fp32 (A operand)
    float* sEh = sR + NN * SRS;        // 128 x EST hi (B operand)
    float* sEl = sEh + NN * EST;       // 128 x EST lo
    const int tid  = threadIdx.x;
    const int lane = tid & 31, warp = tid >> 5;
    const int g = lane >> 2, c = lane & 3;
    const int row = warp * 16 + g;
    const int split = blockIdx.x, b = blockIdx.y;

    constexpr int NT = (EFFD + 7) / 8;   // 13
    float acc[NT][4];
#pragma unroll
    for (int nt = 0; nt < NT; nt++)
#pragma unroll
        for (int q = 0; q < 4; q++) acc[nt][q] = 0.f;

    for (int t = split; t < NTILES; t += KSPLIT) {
        int r0 = t * TILE_R;
        __syncthreads();
        for (int i = tid; i < NN * TILE_R; i += 256) {
            int n = i >> 7, r = i & 127;
            sR[n * SRS + r] = rrel[((size_t)b * NN + n) * RR + r0 + r];
        }
        const float* E = g_effects + ((size_t)b * RR + r0) * EFFD;
        for (int i = tid; i < TILE_R * EST; i += 256) {
            int r = i / EST, cc = i - r * EST;
            float v = (cc < EFFD) ? E[r * EFFD + cc] : 0.f;
            uint32_t h, l;
            split_tf32(v, h, l);
            sEh[i] = __uint_as_float(h);
            sEl[i] = __uint_as_float(l);
        }
        __syncthreads();
        for (int ks = 0; ks < TILE_R; ks += 8) {
            uint32_t ah[4], al[4];
            load_a_frag(sR, row, SRS, ks, c, ah, al);
            const float* Bh = sEh + (ks + c) * EST + g;
            const float* Bl = sEl + (ks + c) * EST + g;
#pragma unroll
            for (int nt = 0; nt < NT; nt++) {
                uint32_t bh0 = __float_as_uint(Bh[nt * 8]);
                uint32_t bh1 = __float_as_uint(Bh[4 * EST + nt * 8]);
                uint32_t bl0 = __float_as_uint(Bl[nt * 8]);
                uint32_t bl1 = __float_as_uint(Bl[4 * EST + nt * 8]);
                mma_tf32(acc[nt], al, bh0, bh1);
                mma_tf32(acc[nt], ah, bl0, bl1);
                mma_tf32(acc[nt], ah, bh0, bh1);
            }
        }
    }

    float* P = g_part + ((size_t)split * BB + b) * NN * EFFD;
#pragma unroll
    for (int nt = 0; nt < NT; nt++) {
#pragma unroll
        for (int q = 0; q < 4; q++) {
            int e = nt * 8 + 2 * c + (q & 1);
            int n = row + ((q & 2) ? 8 : 0);
            if (e < EFFD) P[n * EFFD + e] = acc[nt][q];
        }
    }
}

// ---------------- kernel C: reduce split-K partials ----------------
__global__ void reduce_kernel()
{
    int i = blockIdx.x * blockDim.x + threadIdx.x;
    if (i < BB * NN * EFFD) {
        float s = 0.f;
#pragma unroll
        for (int k = 0; k < KSPLIT; ++k)
            s += g_part[(size_t)k * (BB * NN * EFFD) + i];
        g_er[i] = s;
    }
}

// ---------------- kernel D: final object MLP + sigmoid ----------------
__global__ __launch_bounds__(128)
void final_kernel(const float* __restrict__ objects,
                  const float* __restrict__ ow1, const float* __restrict__ ob1,
                  const float* __restrict__ ow2, const float* __restrict__ ob2,
                  float* __restrict__ out)
{
    __shared__ float y[OIN];
    __shared__ float red[128];
    const int row = blockIdx.x;
    const int t = threadIdx.x;

    if (t < OBJD) y[t] = objects[(size_t)row * OBJD + t];
    if (t < EFFD) y[OBJD + t] = g_er[(size_t)row * EFFD + t];
    __syncthreads();

    float v = 0.f;
    if (t < OHID) {
        float acc = ob1[t];
#pragma unroll 4
        for (int k = 0; k < OIN; ++k) acc = fmaf(y[k], ow1[k * OHID + t], acc);
        v = fmaxf(acc, 0.f) * ow2[t];
    }
    red[t] = v;
    __syncthreads();
    for (int s = 64; s > 0; s >>= 1) {
        if (t < s) red[t] += red[t + s];
        __syncthreads();
    }
    if (t == 0) out[row] = 1.f / (1.f + expf(-(red[0] + ob2[0])));
}

// ---------------- launch ----------------
extern "C" void kernel_launch(void* const* d_in, const int* in_sizes, int n_in,
                              void* d_out, int out_size)
{
    const float* objects = (const float*)d_in[0];
    const float* srel    = (const float*)d_in[1];
    const float* rrel    = (const float*)d_in[2];
    const float* relinfo = (const float*)d_in[3];
    const float* rw1 = (const float*)d_in[4];
    const float* rb1 = (const float*)d_in[5];
    const float* rw2 = (const float*)d_in[6];
    const float* rb2 = (const float*)d_in[7];
    const float* rw3 = (const float*)d_in[8];
    const float* rb3 = (const float*)d_in[9];
    const float* rw4 = (const float*)d_in[10];
    const float* rb4 = (const float*)d_in[11];
    const float* ow1 = (const float*)d_in[12];
    const float* ob1 = (const float*)d_in[13];
    const float* ow2 = (const float*)d_in[14];
    const float* ob2 = (const float*)d_in[15];
    float* out = (float*)d_out;

    // gather smem: 2 activation buffers + max(O^T = 64*132 = 8448, sW hi/lo = 2*40*152 = 12160)
    const int AUX_FLOATS   = 2 * KCH * WST;                                   // 12160
    const int GATHER_SMEM  = (2 * NN * XS + AUX_FLOATS) * (int)sizeof(float); // 216576 B
    const int SCATTER_SMEM = (NN * SRS + 2 * NN * EST) * (int)sizeof(float);  // 174080 B

    cudaFuncSetAttribute(gather_mlp_kernel, cudaFuncAttributeMaxDynamicSharedMemorySize, GATHER_SMEM);
    cudaFuncSetAttribute(scatter_kernel,   cudaFuncAttributeMaxDynamicSharedMemorySize, SCATTER_SMEM);

    gather_mlp_kernel<<<dim3(NTILES, BB), 256, GATHER_SMEM>>>(
        objects, srel, rrel, relinfo,
        rw1, rb1, rw2, rb2, rw3, rb3, rw4, rb4);

    scatter_kernel<<<dim3(KSPLIT, BB), 256, SCATTER_SMEM>>>(rrel);

    reduce_kernel<<<(BB * NN * EFFD + 255) / 256, 256>>>();

    final_kernel<<<BB * NN, 128>>>(objects, ow1, ob1, ow2, ob2, out);
}

// round 9
// speedup vs baseline: 1.8071x; 1.3181x over previous
#include <cuda_runtime.h>
#include <math.h>
#include <cstdint>

// ---------------- problem constants ----------------
#define BB      16
#define NN      128
#define RR      16256
#define OBJD    64
#define RELD    32
#define EFFD    100
#define RHID    150
#define RIN     160      // 2*OBJD + RELD
#define OIN     164      // OBJD + EFFD
#define OHID    100

#define TILE_R  128
#define NTILES  127      // RR / TILE_R
#define KSPLIT  18

// smem strides (floats), conflict-free for the PTX m16n8k8.tf32 fragment patterns:
//  A-operand (scalar ld at row*S + c and +4): S % 32 == 4 -> bank (4g+c) bijective
//  B-operand (scalar ld at c*S + g): S % 32 in {8,24} -> bank (8c+g)/(24c+g) bijective
#define XS      164      // activations (A), 164%32=4
#define OTS     132      // O^T (A, gather), 132%32=4
#define SRS     132      // rel tile (A, scatter), 132%32=4
#define RTS     136      // rel tile (B, gather), 136%32=8
#define WST     152      // weight stage (B, MLP), 152%32=24
#define EST     104      // effects tile (B, scatter), 104%32=8

#define KCH     24       // weight-stage K chunk (multiple of 8), double-buffered
#define WREGS   15       // ceil(KCH*WST/256)

// scratch (device globals: allocation-free per harness rules)
__device__ float g_effects[BB * RR * EFFD];                 // ~104 MB
__device__ float g_part[KSPLIT * BB * NN * EFFD];           // ~14.7 MB
__device__ float g_er[BB * NN * EFFD];                      // ~0.8 MB

// ---------------- tf32 split helpers ----------------
__device__ __forceinline__ void split_tf32(float x, uint32_t& h, uint32_t& l) {
    asm("cvt.rna.tf32.f32 %0, %1;" : "=r"(h) : "f"(x));
    float r = x - __uint_as_float(h);      // exact
    asm("cvt.rna.tf32.f32 %0, %1;" : "=r"(l) : "f"(r));
}

// D += A(16x8,row) * B(8x8,col)  (tf32 inputs, f32 accum)
// PTX layout: a0=(g,c) a1=(g+8,c) a2=(g,c+4) a3=(g+8,c+4); b0=(c,g) b1=(c+4,g)
// C: c0=(g,2c) c1=(g,2c+1) c2=(g+8,2c) c3=(g+8,2c+1)
__device__ __forceinline__ void mma_tf32(float acc[4], const uint32_t a[4],
                                         uint32_t b0, uint32_t b1) {
    asm volatile(
        "mma.sync.aligned.m16n8k8.row.col.f32.tf32.tf32.f32 "
        "{%0,%1,%2,%3}, {%4,%5,%6,%7}, {%8,%9}, {%0,%1,%2,%3};\n"
        : "+f"(acc[0]), "+f"(acc[1]), "+f"(acc[2]), "+f"(acc[3])
        : "r"(a[0]), "r"(a[1]), "r"(a[2]), "r"(a[3]), "r"(b0), "r"(b1));
}

// load + split the A fragment: rows {row,row+8}, k-cols {kbase+c, kbase+c+4}
__device__ __forceinline__ void load_a_frag(const float* A, int row, int stride,
                                            int kbase, int c,
                                            uint32_t ah[4], uint32_t al[4]) {
    const float* Ap = A + row * stride + kbase + c;
    float x0 = Ap[0];
    float x1 = Ap[8 * stride];
    float x2 = Ap[4];
    float x3 = Ap[8 * stride + 4];
    split_tf32(x0, ah[0], al[0]);
    split_tf32(x1, ah[1], al[1]);
    split_tf32(x2, ah[2], al[2]);
    split_tf32(x3, ah[3], al[3]);
}

// ---------------- fused relation-MLP layer (3xTF32, 2x4 warp tiling) ----------------
// A: smem [128, XS] raw fp32. W: global [K, NOUT] fp32, double-buffer-staged split.
// wbuf: 2 x (hi[KCH*WST] + lo[KCH*WST]).
// Each warp: 64 rows (4 m16 tiles), NTW n-tiles. Ends with __syncthreads().
template<int K, int NOUT, bool TO_GLOBAL>
__device__ __forceinline__ void mlp_layer_mma(
    const float* A, const float* __restrict__ W, const float* __restrict__ bias,
    float* Cs, float* Cg, float* wbuf, int tid)
{
    constexpr int NT   = (NOUT + 7) / 8;
    constexpr int NTW  = (NT + 3) / 4;
    constexpr int KPAD = (K + 7) & ~7;
    const int lane = tid & 31, warp = tid >> 5;
    const int g = lane >> 2, c = lane & 3;
    const int mwarp = warp & 1, nwarp = warp >> 1;
    const int mrow  = mwarp * 64 + g;
    const int nbase = nwarp * NTW;

    float acc[4][NTW][4];
#pragma unroll
    for (int mt = 0; mt < 4; mt++)
#pragma unroll
        for (int j = 0; j < NTW; j++)
#pragma unroll
            for (int q = 0; q < 4; q++) acc[mt][j][q] = 0.f;

    float vreg[WREGS];
    int k0 = 0;
    int rows = (KPAD < KCH) ? KPAD : KCH;
    // preload chunk 0 into registers
#pragma unroll
    for (int i = 0; i < WREGS; i++) {
        int idx = tid + i * 256;
        int kk = idx / WST, cc = idx - kk * WST;
        int k = k0 + kk;
        vreg[i] = (kk < rows && k < K && cc < NOUT) ? W[k * NOUT + cc] : 0.f;
    }
    int buf = 0;
    while (k0 < KPAD) {
        float* sWh = wbuf + buf * (2 * KCH * WST);
        float* sWl = sWh + KCH * WST;
        // split + store staged chunk
#pragma unroll
        for (int i = 0; i < WREGS; i++) {
            int idx = tid + i * 256;
            if (idx < rows * WST) {
                uint32_t h, l;
                split_tf32(vreg[i], h, l);
                sWh[idx] = __uint_as_float(h);
                sWl[idx] = __uint_as_float(l);
            }
        }
        __syncthreads();
        // issue next chunk's global loads (overlap with compute below)
        const int k0n = k0 + rows;
        const int rowsn = (KPAD - k0n < KCH) ? (KPAD - k0n) : KCH;
        if (k0n < KPAD) {
#pragma unroll
            for (int i = 0; i < WREGS; i++) {
                int idx = tid + i * 256;
                int kk = idx / WST, cc = idx - kk * WST;
                int k = k0n + kk;
                vreg[i] = (kk < rowsn && k < K && cc < NOUT) ? W[k * NOUT + cc] : 0.f;
            }
        }
        // compute on current chunk
        for (int ks = 0; ks < rows; ks += 8) {
            uint32_t ah[4][4], al[4][4];
#pragma unroll
            for (int mt = 0; mt < 4; mt++)
                load_a_frag(A, mrow + mt * 16, XS, k0 + ks, c, ah[mt], al[mt]);
#pragma unroll
            for (int j = 0; j < NTW; j++) {
                int nt = nbase + j;
                if (nt < NT) {
                    const float* Bh = sWh + (ks + c) * WST + nt * 8 + g;
                    const float* Bl = sWl + (ks + c) * WST + nt * 8 + g;
                    uint32_t bh0 = __float_as_uint(Bh[0]);
                    uint32_t bh1 = __float_as_uint(Bh[4 * WST]);
                    uint32_t bl0 = __float_as_uint(Bl[0]);
                    uint32_t bl1 = __float_as_uint(Bl[4 * WST]);
#pragma unroll
                    for (int mt = 0; mt < 4; mt++) {
                        mma_tf32(acc[mt][j], al[mt], bh0, bh1);
                        mma_tf32(acc[mt][j], ah[mt], bl0, bl1);
                        mma_tf32(acc[mt][j], ah[mt], bh0, bh1);
                    }
                }
            }
        }
        k0 = k0n; rows = rowsn; buf ^= 1;
    }

    // epilogue: c0 (r,2c) c1 (r,2c+1) c2 (r+8,2c) c3 (r+8,2c+1)
#pragma unroll
    for (int mt = 0; mt < 4; mt++)
#pragma unroll
        for (int j = 0; j < NTW; j++) {
            int nt = nbase + j;
            if (nt < NT) {
#pragma unroll
                for (int q = 0; q < 4; q++) {
                    int col = nt * 8 + 2 * c + (q & 1);
                    int r   = mwarp * 64 + mt * 16 + g + ((q & 2) ? 8 : 0);
                    if (TO_GLOBAL) {
                        if (col < NOUT)
                            Cg[r * NOUT + col] = fmaxf(acc[mt][j][q] + __ldg(&bias[col]), 0.f);
                    } else {
                        float o = (col < NOUT) ? fmaxf(acc[mt][j][q] + __ldg(&bias[col]), 0.f) : 0.f;
                        Cs[r * XS + col] = o;
                    }
                }
            }
        }
    __syncthreads();   // Cs visible to next layer; wbuf reads drained
}

// ---------------- kernel A: gather + 4-layer relation MLP ----------------
// grid (NTILES, BB), 256 threads
__global__ __launch_bounds__(256, 1)
void gather_mlp_kernel(const float* __restrict__ objects,
                       const float* __restrict__ srel,
                       const float* __restrict__ rrel,
                       const float* __restrict__ relinfo,
                       const float* __restrict__ rw1, const float* __restrict__ rb1,
                       const float* __restrict__ rw2, const float* __restrict__ rb2,
                       const float* __restrict__ rw3, const float* __restrict__ rb3,
                       const float* __restrict__ rw4, const float* __restrict__ rb4)
{
    extern __shared__ float smem[];
    float* bufX = smem;                    // 128 x XS raw fp32
    float* bufH = bufX + NN * XS;          // 128 x XS; during gather: rel tile [128 x RTS]
    float* wbuf = bufH + NN * XS;          // 2*2*KCH*WST = 14592 floats; gather: O^T [64 x OTS]

    const int tid  = threadIdx.x;
    const int lane = tid & 31, warp = tid >> 5;
    const int g = lane >> 2, c = lane & 3;
    const int t = blockIdx.x, b = blockIdx.y;
    const int r0 = t * TILE_R;

    // stage O^T (raw fp32): wbuf[d*OTS + n] = O[n][d]
    const float* Ob = objects + (size_t)b * NN * OBJD;
    for (int i = tid; i < NN * OBJD; i += 256) {
        int n = i >> 6, d = i & 63;
        wbuf[d * OTS + n] = Ob[i];
    }

    // relation_info -> bufX[:, 128:160]
    const float* RI = relinfo + ((size_t)b * RR + r0) * RELD;
    for (int i = tid; i < TILE_R * RELD; i += 256) {
        int r = i >> 5, cc = i & 31;
        bufX[r * XS + 128 + cc] = RI[i];
    }

    // gather via mma: D[d][r] = sum_n O^T[d][n] * Rel[n][r]
    const int mw = warp & 3;     // d-tile (4 x 16 rows = 64)
    const int rh = warp >> 2;    // r-half (2 x 64 cols)
    for (int pass = 0; pass < 2; ++pass) {
        const float* Rel = pass ? rrel : srel;
        __syncthreads();
        for (int i = tid; i < NN * TILE_R; i += 256) {
            int n = i >> 7, r = i & 127;
            bufH[n * RTS + r] = Rel[((size_t)b * NN + n) * RR + r0 + r];
        }
        __syncthreads();

        float acc[8][4];
#pragma unroll
        for (int nt = 0; nt < 8; nt++)
#pragma unroll
            for (int q = 0; q < 4; q++) acc[nt][q] = 0.f;

        for (int ks = 0; ks < NN; ks += 8) {
            uint32_t ah[4], al[4];
            load_a_frag(wbuf, mw * 16 + g, OTS, ks, c, ah, al);
            const float* Bp = bufH + (ks + c) * RTS + rh * 64 + g;
#pragma unroll
            for (int nt = 0; nt < 8; nt++) {
                uint32_t bh0, bl0, bh1, bl1;
                split_tf32(Bp[nt * 8], bh0, bl0);
                split_tf32(Bp[4 * RTS + nt * 8], bh1, bl1);
                mma_tf32(acc[nt], al, bh0, bh1);
                mma_tf32(acc[nt], ah, bl0, bl1);
                mma_tf32(acc[nt], ah, bh0, bh1);
            }
        }
        // D[d][r] -> bufX[r*XS + pass*64 + d]
#pragma unroll
        for (int nt = 0; nt < 8; nt++) {
#pragma unroll
            for (int q = 0; q < 4; q++) {
                int d = mw * 16 + g + ((q & 2) ? 8 : 0);
                int r = rh * 64 + nt * 8 + 2 * c + (q & 1);
                bufX[r * XS + pass * 64 + d] = acc[nt][q];
            }
        }
    }
    __syncthreads();   // gather done; wbuf free for weight staging

    float* effp = g_effects + ((size_t)b * RR + r0) * EFFD;

    mlp_layer_mma<RIN,  RHID, false>(bufX, rw1, rb1, bufH, nullptr, wbuf, tid);
    mlp_layer_mma<RHID, RHID, false>(bufH, rw2, rb2, bufX, nullptr, wbuf, tid);
    mlp_layer_mma<RHID, RHID, false>(bufX, rw3, rb3, bufH, nullptr, wbuf, tid);
    mlp_layer_mma<RHID, EFFD, true >(bufH, rw4, rb4, nullptr, effp, wbuf, tid);
}

// ---------------- kernel B: scatter (split-K, 3xTF32, 2x4 tiling) ----------------
// grid (KSPLIT, BB), 256 threads.  D[n][e] = sum_r Rel[n][r] * E[r][e]
__global__ __launch_bounds__(256, 1)
void scatter_kernel(const float* __restrict__ rrel)
{
    extern __shared__ float smem[];
    float* sR  = smem;                 // 128 x SRS raw fp32 (A operand)
    float* sEh = sR + NN * SRS;        // 128 x EST hi (B operand)
    float* sEl = sEh + NN * EST;       // 128 x EST lo
    const int tid  = threadIdx.x;
    const int lane = tid & 31, warp = tid >> 5;
    const int g = lane >> 2, c = lane & 3;
    const int mwarp = warp & 1, nwarp = warp >> 1;
    const int mrow  = mwarp * 64 + g;
    const int split = blockIdx.x, b = blockIdx.y;

    constexpr int NT = (EFFD + 7) / 8;   // 13
    constexpr int NTW = (NT + 3) / 4;    // 4
    const int nbase = nwarp * NTW;

    float acc[4][NTW][4];
#pragma unroll
    for (int mt = 0; mt < 4; mt++)
#pragma unroll
        for (int j = 0; j < NTW; j++)
#pragma unroll
            for (int q = 0; q < 4; q++) acc[mt][j][q] = 0.f;

    for (int t = split; t < NTILES; t += KSPLIT) {
        int r0 = t * TILE_R;
        __syncthreads();
        for (int i = tid; i < NN * TILE_R; i += 256) {
            int n = i >> 7, r = i & 127;
            sR[n * SRS + r] = rrel[((size_t)b * NN + n) * RR + r0 + r];
        }
        const float* E = g_effects + ((size_t)b * RR + r0) * EFFD;
        for (int i = tid; i < TILE_R * EST; i += 256) {
            int r = i / EST, cc = i - r * EST;
            float v = (cc < EFFD) ? E[r * EFFD + cc] : 0.f;
            uint32_t h, l;
            split_tf32(v, h, l);
            sEh[i] = __uint_as_float(h);
            sEl[i] = __uint_as_float(l);
        }
        __syncthreads();
        for (int ks = 0; ks < TILE_R; ks += 8) {
            uint32_t ah[4][4], al[4][4];
#pragma unroll
            for (int mt = 0; mt < 4; mt++)
                load_a_frag(sR, mrow + mt * 16, SRS, ks, c, ah[mt], al[mt]);
#pragma unroll
            for (int j = 0; j < NTW; j++) {
                int nt = nbase + j;
                if (nt < NT) {
                    const float* Bh = sEh + (ks + c) * EST + nt * 8 + g;
                    const float* Bl = sEl + (ks + c) * EST + nt * 8 + g;
                    uint32_t bh0 = __float_as_uint(Bh[0]);
                    uint32_t bh1 = __float_as_uint(Bh[4 * EST]);
                    uint32_t bl0 = __float_as_uint(Bl[0]);
                    uint32_t bl1 = __float_as_uint(Bl[4 * EST]);
#pragma unroll
                    for (int mt = 0; mt < 4; mt++) {
                        mma_tf32(acc[mt][j], al[mt], bh0, bh1);
                        mma_tf32(acc[mt][j], ah[mt], bl0, bl1);
                        mma_tf32(acc[mt][j], ah[mt], bh0, bh1);
                    }
                }
            }
        }
    }

    float* P = g_part + ((size_t)split * BB + b) * NN * EFFD;
#pragma unroll
    for (int mt = 0; mt < 4; mt++)
#pragma unroll
        for (int j = 0; j < NTW; j++) {
            int nt = nbase + j;
            if (nt < NT) {
#pragma unroll
                for (int q = 0; q < 4; q++) {
                    int e = nt * 8 + 2 * c + (q & 1);
                    int n = mwarp * 64 + mt * 16 + g + ((q & 2) ? 8 : 0);
                    if (e < EFFD) P[n * EFFD + e] = acc[mt][j][q];
                }
            }
        }
}

// ---------------- kernel C: reduce split-K partials ----------------
__global__ void reduce_kernel()
{
    int i = blockIdx.x * blockDim.x + threadIdx.x;
    if (i < BB * NN * EFFD) {
        float s = 0.f;
#pragma unroll
        for (int k = 0; k < KSPLIT; ++k)
            s += g_part[(size_t)k * (BB * NN * EFFD) + i];
        g_er[i] = s;
    }
}

// ---------------- kernel D: final object MLP + sigmoid ----------------
__global__ __launch_bounds__(128)
void final_kernel(const float* __restrict__ objects,
                  const float* __restrict__ ow1, const float* __restrict__ ob1,
                  const float* __restrict__ ow2, const float* __restrict__ ob2,
                  float* __restrict__ out)
{
    __shared__ float y[OIN];
    __shared__ float red[128];
    const int row = blockIdx.x;
    const int t = threadIdx.x;

    if (t < OBJD) y[t] = objects[(size_t)row * OBJD + t];
    if (t < EFFD) y[OBJD + t] = g_er[(size_t)row * EFFD + t];
    __syncthreads();

    float v = 0.f;
    if (t < OHID) {
        float acc = ob1[t];
#pragma unroll 4
        for (int k = 0; k < OIN; ++k) acc = fmaf(y[k], ow1[k * OHID + t], acc);
        v = fmaxf(acc, 0.f) * ow2[t];
    }
    red[t] = v;
    __syncthreads();
    for (int s = 64; s > 0; s >>= 1) {
        if (t < s) red[t] += red[t + s];
        __syncthreads();
    }
    if (t == 0) out[row] = 1.f / (1.f + expf(-(red[0] + ob2[0])));
}

// ---------------- launch ----------------
extern "C" void kernel_launch(void* const* d_in, const int* in_sizes, int n_in,
                              void* d_out, int out_size)
{
    const float* objects = (const float*)d_in[0];
    const float* srel    = (const float*)d_in[1];
    const float* rrel    = (const float*)d_in[2];
    const float* relinfo = (const float*)d_in[3];
    const float* rw1 = (const float*)d_in[4];
    const float* rb1 = (const float*)d_in[5];
    const float* rw2 = (const float*)d_in[6];
    const float* rb2 = (const float*)d_in[7];
    const float* rw3 = (const float*)d_in[8];
    const float* rb3 = (const float*)d_in[9];
    const float* rw4 = (const float*)d_in[10];
    const float* rb4 = (const float*)d_in[11];
    const float* ow1 = (const float*)d_in[12];
    const float* ob1 = (const float*)d_in[13];
    const float* ow2 = (const float*)d_in[14];
    const float* ob2 = (const float*)d_in[15];
    float* out = (float*)d_out;

    // gather smem: 2 activation buffers + 2x double-buffered (hi+lo) weight stage
    const int AUX_FLOATS   = 2 * 2 * KCH * WST;                               // 14592 (>= 64*OTS=8448)
    const int GATHER_SMEM  = (2 * NN * XS + AUX_FLOATS) * (int)sizeof(float); // 226304 B
    const int SCATTER_SMEM = (NN * SRS + 2 * NN * EST) * (int)sizeof(float);  // 174080 B

    cudaFuncSetAttribute(gather_mlp_kernel, cudaFuncAttributeMaxDynamicSharedMemorySize, GATHER_SMEM);
    cudaFuncSetAttribute(scatter_kernel,   cudaFuncAttributeMaxDynamicSharedMemorySize, SCATTER_SMEM);

    gather_mlp_kernel<<<dim3(NTILES, BB), 256, GATHER_SMEM>>>(
        objects, srel, rrel, relinfo,
        rw1, rb1, rw2, rb2, rw3, rb3, rw4, rb4);

    scatter_kernel<<<dim3(KSPLIT, BB), 256, SCATTER_SMEM>>>(rrel);

    reduce_kernel<<<(BB * NN * EFFD + 255) / 256, 256>>>();

    final_kernel<<<BB * NN, 128>>>(objects, ow1, ob1, ow2, ob2, out);
}

// round 12
// speedup vs baseline: 2.2839x; 1.2639x over previous
#include <cuda_runtime.h>
#include <math.h>
#include <cstdint>

// ---------------- problem constants ----------------
#define BB      16
#define NN      128
#define RR      16256
#define OBJD    64
#define RELD    32
#define EFFD    100
#define RHID    150
#define RIN     160      // 2*OBJD + RELD
#define OIN     164      // OBJD + EFFD
#define OHID    100

#define TILE_R  128
#define NTILES  127      // RR / TILE_R
#define KSPLIT  18
#define THREADS 512      // 16 warps -> 4 warps/SMSP

// smem strides (floats), conflict-free for the PTX m16n8k8.tf32 fragment patterns:
//  A-operand (scalar ld at row*S + c and +4): S % 32 == 4 -> bank (4g+c) bijective
//  B-operand (scalar ld at c*S + g): S % 32 in {8,24} -> bank (8c+g)/(24c+g) bijective
#define XS      164      // activations (A), 164%32=4
#define OTS     132      // O^T (A, gather), 132%32=4
#define SRS     132      // rel tile (A, scatter), 132%32=4
#define RTS     136      // rel tile (B, gather), 136%32=8
#define WST     152      // weight stage (B, MLP), 152%32=24
#define EST     104      // effects tile (B, scatter), 104%32=8

#define KCH     24       // weight-stage K chunk (multiple of 8), double-buffered
#define WREGS   8        // ceil(KCH*WST/THREADS) = ceil(3648/512)

// scratch (device globals: allocation-free per harness rules)
__device__ float g_effects[BB * RR * EFFD];                 // ~104 MB
__device__ float g_part[KSPLIT * BB * NN * EFFD];           // ~14.7 MB
__device__ float g_er[BB * NN * EFFD];                      // ~0.8 MB

// ---------------- tf32 split helpers ----------------
__device__ __forceinline__ void split_tf32(float x, uint32_t& h, uint32_t& l) {
    asm("cvt.rna.tf32.f32 %0, %1;" : "=r"(h) : "f"(x));
    float r = x - __uint_as_float(h);      // exact
    asm("cvt.rna.tf32.f32 %0, %1;" : "=r"(l) : "f"(r));
}

// D += A(16x8,row) * B(8x8,col)  (tf32 inputs, f32 accum)
// PTX layout: a0=(g,c) a1=(g+8,c) a2=(g,c+4) a3=(g+8,c+4); b0=(c,g) b1=(c+4,g)
// C: c0=(g,2c) c1=(g,2c+1) c2=(g+8,2c) c3=(g+8,2c+1)
__device__ __forceinline__ void mma_tf32(float acc[4], const uint32_t a[4],
                                         uint32_t b0, uint32_t b1) {
    asm volatile(
        "mma.sync.aligned.m16n8k8.row.col.f32.tf32.tf32.f32 "
        "{%0,%1,%2,%3}, {%4,%5,%6,%7}, {%8,%9}, {%0,%1,%2,%3};\n"
        : "+f"(acc[0]), "+f"(acc[1]), "+f"(acc[2]), "+f"(acc[3])
        : "r"(a[0]), "r"(a[1]), "r"(a[2]), "r"(a[3]), "r"(b0), "r"(b1));
}

// load + split the A fragment: rows {row,row+8}, k-cols {kbase+c, kbase+c+4}
__device__ __forceinline__ void load_a_frag(const float* A, int row, int stride,
                                            int kbase, int c,
                                            uint32_t ah[4], uint32_t al[4]) {
    const float* Ap = A + row * stride + kbase + c;
    float x0 = Ap[0];
    float x1 = Ap[8 * stride];
    float x2 = Ap[4];
    float x3 = Ap[8 * stride + 4];
    split_tf32(x0, ah[0], al[0]);
    split_tf32(x1, ah[1], al[1]);
    split_tf32(x2, ah[2], al[2]);
    split_tf32(x3, ah[3], al[3]);
}

// ---------------- fused relation-MLP layer (3xTF32, 4x4 warp tiling, 16 warps) ----------------
// A: smem [128, XS] raw fp32. W: global [K, NOUT] fp32, double-buffer-staged split.
// wbuf: 2 x (hi[KCH*WST] + lo[KCH*WST]).
// Warp (mwarp,nwarp) = (warp&3, warp>>2): 32 rows (2 m16 tiles) x NTW n-tiles.
template<int K, int NOUT, bool TO_GLOBAL>
__device__ __forceinline__ void mlp_layer_mma(
    const float* A, const float* __restrict__ W, const float* __restrict__ bias,
    float* Cs, float* Cg, float* wbuf, int tid)
{
    constexpr int NT   = (NOUT + 7) / 8;
    constexpr int NTW  = (NT + 3) / 4;
    constexpr int KPAD = (K + 7) & ~7;
    const int lane = tid & 31, warp = tid >> 5;
    const int g = lane >> 2, c = lane & 3;
    const int mwarp = warp & 3, nwarp = warp >> 2;
    const int mrow  = mwarp * 32 + g;
    const int nbase = nwarp * NTW;

    float acc[2][NTW][4];
#pragma unroll
    for (int mt = 0; mt < 2; mt++)
#pragma unroll
        for (int j = 0; j < NTW; j++)
#pragma unroll
            for (int q = 0; q < 4; q++) acc[mt][j][q] = 0.f;

    float vreg[WREGS];
    int k0 = 0;
    int rows = (KPAD < KCH) ? KPAD : KCH;
    // preload chunk 0 into registers
#pragma unroll
    for (int i = 0; i < WREGS; i++) {
        int idx = tid + i * THREADS;
        int kk = idx / WST, cc = idx - kk * WST;
        int k = k0 + kk;
        vreg[i] = (kk < rows && k < K && cc < NOUT) ? W[k * NOUT + cc] : 0.f;
    }
    int buf = 0;
    while (k0 < KPAD) {
        float* sWh = wbuf + buf * (2 * KCH * WST);
        float* sWl = sWh + KCH * WST;
        // split + store staged chunk
#pragma unroll
        for (int i = 0; i < WREGS; i++) {
            int idx = tid + i * THREADS;
            if (idx < rows * WST) {
                uint32_t h, l;
                split_tf32(vreg[i], h, l);
                sWh[idx] = __uint_as_float(h);
                sWl[idx] = __uint_as_float(l);
            }
        }
        __syncthreads();
        // issue next chunk's global loads (overlap with compute below)
        const int k0n = k0 + rows;
        const int rowsn = (KPAD - k0n < KCH) ? (KPAD - k0n) : KCH;
        if (k0n < KPAD) {
#pragma unroll
            for (int i = 0; i < WREGS; i++) {
                int idx = tid + i * THREADS;
                int kk = idx / WST, cc = idx - kk * WST;
                int k = k0n + kk;
                vreg[i] = (kk < rowsn && k < K && cc < NOUT) ? W[k * NOUT + cc] : 0.f;
            }
        }
        // compute on current chunk
        for (int ks = 0; ks < rows; ks += 8) {
            uint32_t ah[2][4], al[2][4];
#pragma unroll
            for (int mt = 0; mt < 2; mt++)
                load_a_frag(A, mrow + mt * 16, XS, k0 + ks, c, ah[mt], al[mt]);
#pragma unroll
            for (int j = 0; j < NTW; j++) {
                int nt = nbase + j;
                if (nt < NT) {
                    const float* Bh = sWh + (ks + c) * WST + nt * 8 + g;
                    const float* Bl = sWl + (ks + c) * WST + nt * 8 + g;
                    uint32_t bh0 = __float_as_uint(Bh[0]);
                    uint32_t bh1 = __float_as_uint(Bh[4 * WST]);
                    uint32_t bl0 = __float_as_uint(Bl[0]);
                    uint32_t bl1 = __float_as_uint(Bl[4 * WST]);
#pragma unroll
                    for (int mt = 0; mt < 2; mt++) {
                        mma_tf32(acc[mt][j], al[mt], bh0, bh1);
                        mma_tf32(acc[mt][j], ah[mt], bl0, bl1);
                        mma_tf32(acc[mt][j], ah[mt], bh0, bh1);
                    }
                }
            }
        }
        k0 = k0n; rows = rowsn; buf ^= 1;
    }

    // epilogue: c0 (r,2c) c1 (r,2c+1) c2 (r+8,2c) c3 (r+8,2c+1)
#pragma unroll
    for (int mt = 0; mt < 2; mt++)
#pragma unroll
        for (int j = 0; j < NTW; j++) {
            int nt = nbase + j;
            if (nt < NT) {
#pragma unroll
                for (int q = 0; q < 4; q++) {
                    int col = nt * 8 + 2 * c + (q & 1);
                    int r   = mwarp * 32 + mt * 16 + g + ((q & 2) ? 8 : 0);
                    if (TO_GLOBAL) {
                        if (col < NOUT)
                            Cg[r * NOUT + col] = fmaxf(acc[mt][j][q] + __ldg(&bias[col]), 0.f);
                    } else {
                        float o = (col < NOUT) ? fmaxf(acc[mt][j][q] + __ldg(&bias[col]), 0.f) : 0.f;
                        Cs[r * XS + col] = o;
                    }
                }
            }
        }
    __syncthreads();   // Cs visible to next layer; wbuf reads drained
}

// ---------------- kernel A: gather + 4-layer relation MLP ----------------
// grid (NTILES, BB), 512 threads
__global__ __launch_bounds__(THREADS, 1)
void gather_mlp_kernel(const float* __restrict__ objects,
                       const float* __restrict__ srel,
                       const float* __restrict__ rrel,
                       const float* __restrict__ relinfo,
                       const float* __restrict__ rw1, const float* __restrict__ rb1,
                       const float* __restrict__ rw2, const float* __restrict__ rb2,
                       const float* __restrict__ rw3, const float* __restrict__ rb3,
                       const float* __restrict__ rw4, const float* __restrict__ rb4)
{
    extern __shared__ float smem[];
    float* bufX = smem;                    // 128 x XS raw fp32
    float* bufH = bufX + NN * XS;          // 128 x XS; during gather: rel tile [128 x RTS]
    float* wbuf = bufH + NN * XS;          // 2*2*KCH*WST = 14592 floats; gather: O^T [64 x OTS]

    const int tid  = threadIdx.x;
    const int lane = tid & 31, warp = tid >> 5;
    const int g = lane >> 2, c = lane & 3;
    const int t = blockIdx.x, b = blockIdx.y;
    const int r0 = t * TILE_R;

    // stage O^T (raw fp32): wbuf[d*OTS + n] = O[n][d]
    const float* Ob = objects + (size_t)b * NN * OBJD;
    for (int i = tid; i < NN * OBJD; i += THREADS) {
        int n = i >> 6, d = i & 63;
        wbuf[d * OTS + n] = Ob[i];
    }

    // relation_info -> bufX[:, 128:160]
    const float* RI = relinfo + ((size_t)b * RR + r0) * RELD;
    for (int i = tid; i < TILE_R * RELD; i += THREADS) {
        int r = i >> 5, cc = i & 31;
        bufX[r * XS + 128 + cc] = RI[i];
    }

    // gather via mma: D[d][r] = sum_n O^T[d][n] * Rel[n][r]
    // 16 warps: mw = d-tile (4 x m16 = 64 rows), rh = r-quarter (4 x 4 n8 tiles = 128 cols)
    const int mw = warp & 3;
    const int rh = warp >> 2;
    for (int pass = 0; pass < 2; ++pass) {
        const float* Rel = pass ? rrel : srel;
        __syncthreads();
        for (int i = tid; i < NN * TILE_R; i += THREADS) {
            int n = i >> 7, r = i & 127;
            bufH[n * RTS + r] = Rel[((size_t)b * NN + n) * RR + r0 + r];
        }
        __syncthreads();

        float acc[4][4];
#pragma unroll
        for (int nt = 0; nt < 4; nt++)
#pragma unroll
            for (int q = 0; q < 4; q++) acc[nt][q] = 0.f;

        for (int ks = 0; ks < NN; ks += 8) {
            uint32_t ah[4], al[4];
            load_a_frag(wbuf, mw * 16 + g, OTS, ks, c, ah, al);
            const float* Bp = bufH + (ks + c) * RTS + rh * 32 + g;
#pragma unroll
            for (int nt = 0; nt < 4; nt++) {
                uint32_t bh0, bl0, bh1, bl1;
                split_tf32(Bp[nt * 8], bh0, bl0);
                split_tf32(Bp[4 * RTS + nt * 8], bh1, bl1);
                mma_tf32(acc[nt], al, bh0, bh1);
                mma_tf32(acc[nt], ah, bl0, bl1);
                mma_tf32(acc[nt], ah, bh0, bh1);
            }
        }
        // D[d][r] -> bufX[r*XS + pass*64 + d]
#pragma unroll
        for (int nt = 0; nt < 4; nt++) {
#pragma unroll
            for (int q = 0; q < 4; q++) {
                int d = mw * 16 + g + ((q & 2) ? 8 : 0);
                int r = rh * 32 + nt * 8 + 2 * c + (q & 1);
                bufX[r * XS + pass * 64 + d] = acc[nt][q];
            }
        }
    }
    __syncthreads();   // gather done; wbuf free for weight staging

    float* effp = g_effects + ((size_t)b * RR + r0) * EFFD;

    mlp_layer_mma<RIN,  RHID, false>(bufX, rw1, rb1, bufH, nullptr, wbuf, tid);
    mlp_layer_mma<RHID, RHID, false>(bufH, rw2, rb2, bufX, nullptr, wbuf, tid);
    mlp_layer_mma<RHID, RHID, false>(bufX, rw3, rb3, bufH, nullptr, wbuf, tid);
    mlp_layer_mma<RHID, EFFD, true >(bufH, rw4, rb4, nullptr, effp, wbuf, tid);
}

// ---------------- kernel B: scatter (split-K, 3xTF32, 4x4 tiling, 16 warps) ----------------
// grid (KSPLIT, BB), 512 threads.  D[n][e] = sum_r Rel[n][r] * E[r][e]
__global__ __launch_bounds__(THREADS, 1)
void scatter_kernel(const float* __restrict__ rrel)
{
    extern __shared__ float smem[];
    float* sR  = smem;                 // 128 x SRS raw fp32 (A operand)
    float* sEh = sR + NN * SRS;        // 128 x EST hi (B operand)
    float* sEl = sEh + NN * EST;       // 128 x EST lo
    const int tid  = threadIdx.x;
    const int lane = tid & 31, warp = tid >> 5;
    const int g = lane >> 2, c = lane & 3;
    const int mwarp = warp & 3, nwarp = warp >> 2;
    const int mrow  = mwarp * 32 + g;
    const int split = blockIdx.x, b = blockIdx.y;

    constexpr int NT = (EFFD + 7) / 8;   // 13
    constexpr int NTW = (NT + 3) / 4;    // 4
    const int nbase = nwarp * NTW;

    float acc[2][NTW][4];
#pragma unroll
    for (int mt = 0; mt < 2; mt++)
#pragma unroll
        for (int j = 0; j < NTW; j++)
#pragma unroll
            for (int q = 0; q < 4; q++) acc[mt][j][q] = 0.f;

    for (int t = split; t < NTILES; t += KSPLIT) {
        int r0 = t * TILE_R;
        __syncthreads();
        for (int i = tid; i < NN * TILE_R; i += THREADS) {
            int n = i >> 7, r = i & 127;
            sR[n * SRS + r] = rrel[((size_t)b * NN + n) * RR + r0 + r];
        }
        const float* E = g_effects + ((size_t)b * RR + r0) * EFFD;
        for (int i = tid; i < TILE_R * EST; i += THREADS) {
            int r = i / EST, cc = i - r * EST;
            float v = (cc < EFFD) ? E[r * EFFD + cc] : 0.f;
            uint32_t h, l;
            split_tf32(v, h, l);
            sEh[i] = __uint_as_float(h);
            sEl[i] = __uint_as_float(l);
        }
        __syncthreads();
        for (int ks = 0; ks < TILE_R; ks += 8) {
            uint32_t ah[2][4], al[2][4];
#pragma unroll
            for (int mt = 0; mt < 2; mt++)
                load_a_frag(sR, mrow + mt * 16, SRS, ks, c, ah[mt], al[mt]);
#pragma unroll
            for (int j = 0; j < NTW; j++) {
                int nt = nbase + j;
                if (nt < NT) {
                    const float* Bh = sEh + (ks + c) * EST + nt * 8 + g;
                    const float* Bl = sEl + (ks + c) * EST + nt * 8 + g;
                    uint32_t bh0 = __float_as_uint(Bh[0]);
                    uint32_t bh1 = __float_as_uint(Bh[4 * EST]);
                    uint32_t bl0 = __float_as_uint(Bl[0]);
                    uint32_t bl1 = __float_as_uint(Bl[4 * EST]);
#pragma unroll
                    for (int mt = 0; mt < 2; mt++) {
                        mma_tf32(acc[mt][j], al[mt], bh0, bh1);
                        mma_tf32(acc[mt][j], ah[mt], bl0, bl1);
                        mma_tf32(acc[mt][j], ah[mt], bh0, bh1);
                    }
                }
            }
        }
    }

    float* P = g_part + ((size_t)split * BB + b) * NN * EFFD;
#pragma unroll
    for (int mt = 0; mt < 2; mt++)
#pragma unroll
        for (int j = 0; j < NTW; j++) {
            int nt = nbase + j;
            if (nt < NT) {
#pragma unroll
                for (int q = 0; q < 4; q++) {
                    int e = nt * 8 + 2 * c + (q & 1);
                    int n = mwarp * 32 + mt * 16 + g + ((q & 2) ? 8 : 0);
                    if (e < EFFD) P[n * EFFD + e] = acc[mt][j][q];
                }
            }
        }
}

// ---------------- kernel C: reduce split-K partials ----------------
__global__ void reduce_kernel()
{
    int i = blockIdx.x * blockDim.x + threadIdx.x;
    if (i < BB * NN * EFFD) {
        float s = 0.f;
#pragma unroll
        for (int k = 0; k < KSPLIT; ++k)
            s += g_part[(size_t)k * (BB * NN * EFFD) + i];
        g_er[i] = s;
    }
}

// ---------------- kernel D: final object MLP + sigmoid ----------------
__global__ __launch_bounds__(128)
void final_kernel(const float* __restrict__ objects,
                  const float* __restrict__ ow1, const float* __restrict__ ob1,
                  const float* __restrict__ ow2, const float* __restrict__ ob2,
                  float* __restrict__ out)
{
    __shared__ float y[OIN];
    __shared__ float red[128];
    const int row = blockIdx.x;
    const int t = threadIdx.x;

    if (t < OBJD) y[t] = objects[(size_t)row * OBJD + t];
    if (t < EFFD) y[OBJD + t] = g_er[(size_t)row * EFFD + t];
    __syncthreads();

    float v = 0.f;
    if (t < OHID) {
        float acc = ob1[t];
#pragma unroll 4
        for (int k = 0; k < OIN; ++k) acc = fmaf(y[k], ow1[k * OHID + t], acc);
        v = fmaxf(acc, 0.f) * ow2[t];
    }
    red[t] = v;
    __syncthreads();
    for (int s = 64; s > 0; s >>= 1) {
        if (t < s) red[t] += red[t + s];
        __syncthreads();
    }
    if (t == 0) out[row] = 1.f / (1.f + expf(-(red[0] + ob2[0])));
}

// ---------------- launch ----------------
extern "C" void kernel_launch(void* const* d_in, const int* in_sizes, int n_in,
                              void* d_out, int out_size)
{
    const float* objects = (const float*)d_in[0];
    const float* srel    = (const float*)d_in[1];
    const float* rrel    = (const float*)d_in[2];
    const float* relinfo = (const float*)d_in[3];
    const float* rw1 = (const float*)d_in[4];
    const float* rb1 = (const float*)d_in[5];
    const float* rw2 = (const float*)d_in[6];
    const float* rb2 = (const float*)d_in[7];
    const float* rw3 = (const float*)d_in[8];
    const float* rb3 = (const float*)d_in[9];
    const float* rw4 = (const float*)d_in[10];
    const float* rb4 = (const float*)d_in[11];
    const float* ow1 = (const float*)d_in[12];
    const float* ob1 = (const float*)d_in[13];
    const float* ow2 = (const float*)d_in[14];
    const float* ob2 = (const float*)d_in[15];
    float* out = (float*)d_out;

    // gather smem: 2 activation buffers + 2x double-buffered (hi+lo) weight stage
    const int AUX_FLOATS   = 2 * 2 * KCH * WST;                               // 14592 (>= 64*OTS=8448)
    const int GATHER_SMEM  = (2 * NN * XS + AUX_FLOATS) * (int)sizeof(float); // 226304 B
    const int SCATTER_SMEM = (NN * SRS + 2 * NN * EST) * (int)sizeof(float);  // 174080 B

    cudaFuncSetAttribute(gather_mlp_kernel, cudaFuncAttributeMaxDynamicSharedMemorySize, GATHER_SMEM);
    cudaFuncSetAttribute(scatter_kernel,   cudaFuncAttributeMaxDynamicSharedMemorySize, SCATTER_SMEM);

    gather_mlp_kernel<<<dim3(NTILES, BB), THREADS, GATHER_SMEM>>>(
        objects, srel, rrel, relinfo,
        rw1, rb1, rw2, rb2, rw3, rb3, rw4, rb4);

    scatter_kernel<<<dim3(KSPLIT, BB), THREADS, SCATTER_SMEM>>>(rrel);

    reduce_kernel<<<(BB * NN * EFFD + 255) / 256, 256>>>();

    final_kernel<<<BB * NN, 128>>>(objects, ow1, ob1, ow2, ob2, out);
}

// round 14
// speedup vs baseline: 2.6963x; 1.1806x over previous
#include <cuda_runtime.h>
#include <math.h>
#include <cstdint>

// ---------------- problem constants ----------------
#define BB      16
#define NN      128
#define RR      16256
#define OBJD    64
#define RELD    32
#define EFFD    100
#define RHID    150
#define RIN     160      // 2*OBJD + RELD
#define OIN     164      // OBJD + EFFD
#define OHID    100

#define TILE_R  128
#define NTILES  127      // RR / TILE_R
#define KSPLIT  9
#define THREADS 512      // 16 warps -> 4 warps/SMSP

// smem strides (floats), conflict-free for the PTX m16n8k8.tf32 fragment patterns:
//  A-operand (scalar ld at row*S + c and +4): S % 32 == 4 -> bank (4g+c) bijective
//  B-operand (scalar ld at c*S + g): S % 32 in {8,24} -> bank (8c+g)/(24c+g) bijective
#define XS      164      // activations (A), 164%32=4
#define OTS     132      // O^T (A, gather), 132%32=4
#define SRS     132      // rel tile (A, scatter), 132%32=4
#define RTS     136      // rel tile (B, gather), 136%32=8
#define WST     152      // weight stage (B, MLP), 152%32=24
#define EST     104      // effects tile (B, scatter), 104%32=8

#define KPADW   160      // all MLP layers padded to K=160 (10 chunks of 16)
#define WCHUNKS 10
#define CF      (16 * WST)     // floats per chunk per (hi|lo) = 2432
#define CW      (CF / 4)       // 16B words per chunk = 608
#define WOFF    (KPADW * WST)  // per-layer padded weight floats = 24320

// scratch (device globals: allocation-free per harness rules)
__device__ float g_effects[BB * RR * EFFD];                 // ~104 MB
__device__ float g_part[KSPLIT * BB * NN * EFFD];           // ~7.4 MB
__device__ float g_wh[4 * WOFF];                            // pre-split weights hi
__device__ float g_wl[4 * WOFF];                            // pre-split weights lo

// ---------------- tf32 split helpers ----------------
__device__ __forceinline__ void split_tf32(float x, uint32_t& h, uint32_t& l) {
    asm("cvt.rna.tf32.f32 %0, %1;" : "=r"(h) : "f"(x));
    float r = x - __uint_as_float(h);      // exact
    asm("cvt.rna.tf32.f32 %0, %1;" : "=r"(l) : "f"(r));
}

// D += A(16x8,row) * B(8x8,col)  (tf32 inputs, f32 accum)
// PTX layout: a0=(g,c) a1=(g+8,c) a2=(g,c+4) a3=(g+8,c+4); b0=(c,g) b1=(c+4,g)
// C: c0=(g,2c) c1=(g,2c+1) c2=(g+8,2c) c3=(g+8,2c+1)
__device__ __forceinline__ void mma_tf32(float acc[4], const uint32_t a[4],
                                         uint32_t b0, uint32_t b1) {
    asm volatile(
        "mma.sync.aligned.m16n8k8.row.col.f32.tf32.tf32.f32 "
        "{%0,%1,%2,%3}, {%4,%5,%6,%7}, {%8,%9}, {%0,%1,%2,%3};\n"
        : "+f"(acc[0]), "+f"(acc[1]), "+f"(acc[2]), "+f"(acc[3])
        : "r"(a[0]), "r"(a[1]), "r"(a[2]), "r"(a[3]), "r"(b0), "r"(b1));
}

// load + split the A fragment: rows {row,row+8}, k-cols {kbase+c, kbase+c+4}
__device__ __forceinline__ void load_a_frag(const float* A, int row, int stride,
                                            int kbase, int c,
                                            uint32_t ah[4], uint32_t al[4]) {
    const float* Ap = A + row * stride + kbase + c;
    float x0 = Ap[0];
    float x1 = Ap[8 * stride];
    float x2 = Ap[4];
    float x3 = Ap[8 * stride + 4];
    split_tf32(x0, ah[0], al[0]);
    split_tf32(x1, ah[1], al[1]);
    split_tf32(x2, ah[2], al[2]);
    split_tf32(x3, ah[3], al[3]);
}

// ---------------- cp.async helpers ----------------
__device__ __forceinline__ void cpasync16(float* dst, const float* src) {
    unsigned d = (unsigned)__cvta_generic_to_shared(dst);
    asm volatile("cp.async.cg.shared.global [%0], [%1], 16;\n" :: "r"(d), "l"(src));
}
__device__ __forceinline__ void cpasync_commit() {
    asm volatile("cp.async.commit_group;\n" ::: "memory");
}
template<int N>
__device__ __forceinline__ void cpasync_wait() {
    asm volatile("cp.async.wait_group %0;\n" :: "n"(N) : "memory");
}

// ---------------- setup: pre-split all MLP weights (padded, zero-filled) ----------------
__global__ void split_weights_kernel(const float* __restrict__ rw1,
                                     const float* __restrict__ rw2,
                                     const float* __restrict__ rw3,
                                     const float* __restrict__ rw4)
{
    int i = blockIdx.x * blockDim.x + threadIdx.x;
    if (i >= 4 * WOFF) return;
    int layer = i / WOFF, off = i - layer * WOFF;
    int k = off / WST, cc = off - k * WST;
    const float* W; int K, NOUT;
    switch (layer) {
        case 0:  W = rw1; K = RIN;  NOUT = RHID; break;
        case 1:  W = rw2; K = RHID; NOUT = RHID; break;
        case 2:  W = rw3; K = RHID; NOUT = RHID; break;
        default: W = rw4; K = RHID; NOUT = EFFD; break;
    }
    float v = (k < K && cc < NOUT) ? W[k * NOUT + cc] : 0.f;
    uint32_t h, l;
    split_tf32(v, h, l);
    g_wh[i] = __uint_as_float(h);
    g_wl[i] = __uint_as_float(l);
}

// ---------------- fused relation-MLP layer (3xTF32, cp.async 3-stage weights) ----------------
// A: smem [128, XS] raw fp32 (cols [0,160) valid). Weights: g_wh/g_wl + layer*WOFF.
// wbuf: 3 stages x (hi[CF] + lo[CF]).
template<int NOUT, bool TO_GLOBAL>
__device__ __forceinline__ void mlp_layer_mma(
    const float* A, int layer, const float* __restrict__ bias,
    float* Cs, float* Cg, float* wbuf, int tid)
{
    constexpr int NT  = (NOUT + 7) / 8;
    constexpr int NTW = (NT + 3) / 4;
    const int lane = tid & 31, warp = tid >> 5;
    const int g = lane >> 2, c = lane & 3;
    const int mwarp = warp & 3, nwarp = warp >> 2;
    const int mrow  = mwarp * 32 + g;
    const int nbase = nwarp * NTW;

    const float* Wh = g_wh + layer * WOFF;
    const float* Wl = g_wl + layer * WOFF;

    float acc[2][NTW][4];
#pragma unroll
    for (int mt = 0; mt < 2; mt++)
#pragma unroll
        for (int j = 0; j < NTW; j++)
#pragma unroll
            for (int q = 0; q < 4; q++) acc[mt][j][q] = 0.f;

    // stage copy: chunk -> stage (hi then lo), 2*CW 16B words
    auto issue_copy = [&](int chunk, int stage) {
        float* sh = wbuf + stage * (2 * CF);
        const float* gh = Wh + chunk * CF;
        const float* gl = Wl + chunk * CF;
        for (int idx = tid; idx < 2 * CW; idx += THREADS) {
            if (idx < CW) cpasync16(sh + idx * 4, gh + idx * 4);
            else          cpasync16(sh + CF + (idx - CW) * 4, gl + (idx - CW) * 4);
        }
    };

    issue_copy(0, 0); cpasync_commit();
    issue_copy(1, 1); cpasync_commit();

    for (int i = 0; i < WCHUNKS; i++) {
        cpasync_wait<1>();       // chunk i landed
        __syncthreads();         // visible to all; prior compute done
        if (i + 2 < WCHUNKS) issue_copy(i + 2, (i + 2) % 3);
        cpasync_commit();        // always (group alignment)

        const float* sWh = wbuf + (i % 3) * (2 * CF);
        const float* sWl = sWh + CF;
        const int k0 = i * 16;
#pragma unroll
        for (int ks = 0; ks < 16; ks += 8) {
            uint32_t ah[2][4], al[2][4];
#pragma unroll
            for (int mt = 0; mt < 2; mt++)
                load_a_frag(A, mrow + mt * 16, XS, k0 + ks, c, ah[mt], al[mt]);
#pragma unroll
            for (int j = 0; j < NTW; j++) {
                int nt = nbase + j;
                if (nt < NT) {
                    const float* Bh = sWh + (ks + c) * WST + nt * 8 + g;
                    const float* Bl = sWl + (ks + c) * WST + nt * 8 + g;
                    uint32_t bh0 = __float_as_uint(Bh[0]);
                    uint32_t bh1 = __float_as_uint(Bh[4 * WST]);
                    uint32_t bl0 = __float_as_uint(Bl[0]);
                    uint32_t bl1 = __float_as_uint(Bl[4 * WST]);
#pragma unroll
                    for (int mt = 0; mt < 2; mt++) {
                        mma_tf32(acc[mt][j], al[mt], bh0, bh1);
                        mma_tf32(acc[mt][j], ah[mt], bl0, bl1);
                        mma_tf32(acc[mt][j], ah[mt], bh0, bh1);
                    }
                }
            }
        }
    }

    // epilogue: c0 (r,2c) c1 (r,2c+1) c2 (r+8,2c) c3 (r+8,2c+1)
#pragma unroll
    for (int mt = 0; mt < 2; mt++)
#pragma unroll
        for (int j = 0; j < NTW; j++) {
            int nt = nbase + j;
            if (nt < NT) {
#pragma unroll
                for (int q = 0; q < 4; q++) {
                    int col = nt * 8 + 2 * c + (q & 1);
                    int r   = mwarp * 32 + mt * 16 + g + ((q & 2) ? 8 : 0);
                    if (TO_GLOBAL) {
                        if (col < NOUT)
                            Cg[r * NOUT + col] = fmaxf(acc[mt][j][q] + __ldg(&bias[col]), 0.f);
                    } else {
                        float o = (col < NOUT) ? fmaxf(acc[mt][j][q] + __ldg(&bias[col]), 0.f) : 0.f;
                        Cs[r * XS + col] = o;
                    }
                }
            }
        }
    if (!TO_GLOBAL && NT * 8 < KPADW) {
        // zero-pad cols [NT*8, 160) so next layer's padded-K reads are exact zeros
        constexpr int PADW = KPADW - NT * 8;
        for (int idx = tid; idx < NN * PADW; idx += THREADS) {
            int r = idx / PADW, cc = idx - r * PADW;
            Cs[r * XS + NT * 8 + cc] = 0.f;
        }
    }
    __syncthreads();   // Cs visible to next layer; wbuf reads drained
}

// ---------------- kernel A: gather + 4-layer relation MLP ----------------
// grid (NTILES, BB), 512 threads
__global__ __launch_bounds__(THREADS, 1)
void gather_mlp_kernel(const float* __restrict__ objects,
                       const float* __restrict__ srel,
                       const float* __restrict__ rrel,
                       const float* __restrict__ relinfo,
                       const float* __restrict__ rb1, const float* __restrict__ rb2,
                       const float* __restrict__ rb3, const float* __restrict__ rb4)
{
    extern __shared__ float smem[];
    float* bufX = smem;                    // 128 x XS raw fp32
    float* bufH = bufX + NN * XS;          // 128 x XS; during gather: rel tile [128 x RTS]
    float* wbuf = bufH + NN * XS;          // 3*2*CF = 14592 floats; gather: O^T [64 x OTS]

    const int tid  = threadIdx.x;
    const int lane = tid & 31, warp = tid >> 5;
    const int g = lane >> 2, c = lane & 3;
    const int t = blockIdx.x, b = blockIdx.y;
    const int r0 = t * TILE_R;

    // issue pass-0 rel tile copy FIRST (overlaps with O^T / relinfo staging)
    {
        const float* Rel = srel;
        for (int idx = tid; idx < NN * 32; idx += THREADS) {
            int n = idx >> 5, w = idx & 31;
            cpasync16(bufH + n * RTS + w * 4,
                      Rel + ((size_t)b * NN + n) * RR + r0 + w * 4);
        }
        cpasync_commit();
    }

    // stage O^T (raw fp32): wbuf[d*OTS + n] = O[n][d]
    const float* Ob = objects + (size_t)b * NN * OBJD;
    for (int i = tid; i < NN * OBJD; i += THREADS) {
        int n = i >> 6, d = i & 63;
        wbuf[d * OTS + n] = Ob[i];
    }

    // relation_info -> bufX[:, 128:160]
    const float* RI = relinfo + ((size_t)b * RR + r0) * RELD;
    for (int i = tid; i < TILE_R * RELD; i += THREADS) {
        int r = i >> 5, cc = i & 31;
        bufX[r * XS + 128 + cc] = RI[i];
    }

    // gather via mma: D[d][r] = sum_n O^T[d][n] * Rel[n][r]
    // 16 warps: mw = d-tile (4 x m16 = 64 rows), rh = r-quarter (4 x 4 n8 tiles)
    const int mw = warp & 3;
    const int rh = warp >> 2;
    for (int pass = 0; pass < 2; ++pass) {
        cpasync_wait<0>();
        __syncthreads();       // rel tile + (pass0: O^T, relinfo) staged for all

        float acc[4][4];
#pragma unroll
        for (int nt = 0; nt < 4; nt++)
#pragma unroll
            for (int q = 0; q < 4; q++) acc[nt][q] = 0.f;

        for (int ks = 0; ks < NN; ks += 8) {
            uint32_t ah[4], al[4];
            load_a_frag(wbuf, mw * 16 + g, OTS, ks, c, ah, al);
            const float* Bp = bufH + (ks + c) * RTS + rh * 32 + g;
#pragma unroll
            for (int nt = 0; nt < 4; nt++) {
                uint32_t bh0, bl0, bh1, bl1;
                split_tf32(Bp[nt * 8], bh0, bl0);
                split_tf32(Bp[4 * RTS + nt * 8], bh1, bl1);
                mma_tf32(acc[nt], al, bh0, bh1);
                mma_tf32(acc[nt], ah, bl0, bl1);
                mma_tf32(acc[nt], ah, bh0, bh1);
            }
        }
        // D[d][r] -> bufX[r*XS + pass*64 + d]
#pragma unroll
        for (int nt = 0; nt < 4; nt++) {
#pragma unroll
            for (int q = 0; q < 4; q++) {
                int d = mw * 16 + g + ((q & 2) ? 8 : 0);
                int r = rh * 32 + nt * 8 + 2 * c + (q & 1);
                bufX[r * XS + pass * 64 + d] = acc[nt][q];
            }
        }
        if (pass == 0) {
            __syncthreads();   // all warps done reading bufH (pass-0 tile)
            for (int idx = tid; idx < NN * 32; idx += THREADS) {
                int n = idx >> 5, w = idx & 31;
                cpasync16(bufH + n * RTS + w * 4,
                          rrel + ((size_t)b * NN + n) * RR + r0 + w * 4);
            }
            cpasync_commit();
        }
    }
    __syncthreads();   // gather done; wbuf (O^T) + bufH free

    float* effp = g_effects + ((size_t)b * RR + r0) * EFFD;

    mlp_layer_mma<RHID, false>(bufX, 0, rb1, bufH, nullptr, wbuf, tid);
    mlp_layer_mma<RHID, false>(bufH, 1, rb2, bufX, nullptr, wbuf, tid);
    mlp_layer_mma<RHID, false>(bufX, 2, rb3, bufH, nullptr, wbuf, tid);
    mlp_layer_mma<EFFD, true >(bufH, 3, rb4, nullptr, effp, wbuf, tid);
}

// ---------------- kernel B: scatter (split-K, 3xTF32, cp.async staging) ----------------
// grid (KSPLIT, BB), 512 threads.  D[n][e] = sum_r Rel[n][r] * E[r][e]
__global__ __launch_bounds__(THREADS, 1)
void scatter_kernel(const float* __restrict__ rrel)
{
    extern __shared__ float smem[];
    float* sR  = smem;                 // 128 x SRS raw fp32 (A operand)
    float* sEh = sR + NN * SRS;        // 128 x EST hi (B operand)
    float* sEl = sEh + NN * EST;       // 128 x EST lo
    const int tid  = threadIdx.x;
    const int lane = tid & 31, warp = tid >> 5;
    const int g = lane >> 2, c = lane & 3;
    const int mwarp = warp & 3, nwarp = warp >> 2;
    const int mrow  = mwarp * 32 + g;
    const int split = blockIdx.x, b = blockIdx.y;

    constexpr int NT = (EFFD + 7) / 8;   // 13
    constexpr int NTW = (NT + 3) / 4;    // 4
    const int nbase = nwarp * NTW;

    float acc[2][NTW][4];
#pragma unroll
    for (int mt = 0; mt < 2; mt++)
#pragma unroll
        for (int j = 0; j < NTW; j++)
#pragma unroll
            for (int q = 0; q < 4; q++) acc[mt][j][q] = 0.f;

    for (int t = split; t < NTILES; t += KSPLIT) {
        int r0 = t * TILE_R;
        __syncthreads();    // prior tile's compute done before restaging
        // rel tile via cp.async (overlaps with effects staging below)
        for (int idx = tid; idx < NN * 32; idx += THREADS) {
            int n = idx >> 5, w = idx & 31;
            cpasync16(sR + n * SRS + w * 4,
                      rrel + ((size_t)b * NN + n) * RR + r0 + w * 4);
        }
        cpasync_commit();
        // effects tile: LDG + split + STS
        const float* E = g_effects + ((size_t)b * RR + r0) * EFFD;
        for (int i = tid; i < TILE_R * EST; i += THREADS) {
            int r = i / EST, cc = i - r * EST;
            float v = (cc < EFFD) ? E[r * EFFD + cc] : 0.f;
            uint32_t h, l;
            split_tf32(v, h, l);
            sEh[i] = __uint_as_float(h);
            sEl[i] = __uint_as_float(l);
        }
        cpasync_wait<0>();
        __syncthreads();
        for (int ks = 0; ks < TILE_R; ks += 8) {
            uint32_t ah[2][4], al[2][4];
#pragma unroll
            for (int mt = 0; mt < 2; mt++)
                load_a_frag(sR, mrow + mt * 16, SRS, ks, c, ah[mt], al[mt]);
#pragma unroll
            for (int j = 0; j < NTW; j++) {
                int nt = nbase + j;
                if (nt < NT) {
                    const float* Bh = sEh + (ks + c) * EST + nt * 8 + g;
                    const float* Bl = sEl + (ks + c) * EST + nt * 8 + g;
                    uint32_t bh0 = __float_as_uint(Bh[0]);
                    uint32_t bh1 = __float_as_uint(Bh[4 * EST]);
                    uint32_t bl0 = __float_as_uint(Bl[0]);
                    uint32_t bl1 = __float_as_uint(Bl[4 * EST]);
#pragma unroll
                    for (int mt = 0; mt < 2; mt++) {
                        mma_tf32(acc[mt][j], al[mt], bh0, bh1);
                        mma_tf32(acc[mt][j], ah[mt], bl0, bl1);
                        mma_tf32(acc[mt][j], ah[mt], bh0, bh1);
                    }
                }
            }
        }
    }

    float* P = g_part + ((size_t)split * BB + b) * NN * EFFD;
#pragma unroll
    for (int mt = 0; mt < 2; mt++)
#pragma unroll
        for (int j = 0; j < NTW; j++) {
            int nt = nbase + j;
            if (nt < NT) {
#pragma unroll
                for (int q = 0; q < 4; q++) {
                    int e = nt * 8 + 2 * c + (q & 1);
                    int n = mwarp * 32 + mt * 16 + g + ((q & 2) ? 8 : 0);
                    if (e < EFFD) P[n * EFFD + e] = acc[mt][j][q];
                }
            }
        }
}

// ---------------- kernel D: fused reduce + final object MLP + sigmoid ----------------
__global__ __launch_bounds__(128)
void final_kernel(const float* __restrict__ objects,
                  const float* __restrict__ ow1, const float* __restrict__ ob1,
                  const float* __restrict__ ow2, const float* __restrict__ ob2,
                  float* __restrict__ out)
{
    __shared__ float y[OIN];
    __shared__ float red[128];
    const int row = blockIdx.x;
    const int t = threadIdx.x;

    if (t < OBJD) y[t] = objects[(size_t)row * OBJD + t];
    if (t < EFFD) {
        float s = 0.f;
#pragma unroll
        for (int k = 0; k < KSPLIT; ++k)
            s += g_part[(size_t)k * (BB * NN * EFFD) + (size_t)row * EFFD + t];
        y[OBJD + t] = s;
    }
    __syncthreads();

    float v = 0.f;
    if (t < OHID) {
        float acc = ob1[t];
#pragma unroll 4
        for (int k = 0; k < OIN; ++k) acc = fmaf(y[k], ow1[k * OHID + t], acc);
        v = fmaxf(acc, 0.f) * ow2[t];
    }
    red[t] = v;
    __syncthreads();
    for (int s = 64; s > 0; s >>= 1) {
        if (t < s) red[t] += red[t + s];
        __syncthreads();
    }
    if (t == 0) out[row] = 1.f / (1.f + expf(-(red[0] + ob2[0])));
}

// ---------------- launch ----------------
extern "C" void kernel_launch(void* const* d_in, const int* in_sizes, int n_in,
                              void* d_out, int out_size)
{
    const float* objects = (const float*)d_in[0];
    const float* srel    = (const float*)d_in[1];
    const float* rrel    = (const float*)d_in[2];
    const float* relinfo = (const float*)d_in[3];
    const float* rw1 = (const float*)d_in[4];
    const float* rb1 = (const float*)d_in[5];
    const float* rw2 = (const float*)d_in[6];
    const float* rb2 = (const float*)d_in[7];
    const float* rw3 = (const float*)d_in[8];
    const float* rb3 = (const float*)d_in[9];
    const float* rw4 = (const float*)d_in[10];
    const float* rb4 = (const float*)d_in[11];
    const float* ow1 = (const float*)d_in[12];
    const float* ob1 = (const float*)d_in[13];
    const float* ow2 = (const float*)d_in[14];
    const float* ob2 = (const float*)d_in[15];
    float* out = (float*)d_out;

    // gather smem: 2 activation buffers + 3-stage (hi+lo) weight pipeline
    const int AUX_FLOATS   = 3 * 2 * CF;                                      // 14592 (>= 64*OTS=8448)
    const int GATHER_SMEM  = (2 * NN * XS + AUX_FLOATS) * (int)sizeof(float); // 226304 B
    const int SCATTER_SMEM = (NN * SRS + 2 * NN * EST) * (int)sizeof(float);  // 174080 B

    cudaFuncSetAttribute(gather_mlp_kernel, cudaFuncAttributeMaxDynamicSharedMemorySize, GATHER_SMEM);
    cudaFuncSetAttribute(scatter_kernel,   cudaFuncAttributeMaxDynamicSharedMemorySize, SCATTER_SMEM);

    split_weights_kernel<<<(4 * WOFF + 255) / 256, 256>>>(rw1, rw2, rw3, rw4);

    gather_mlp_kernel<<<dim3(NTILES, BB), THREADS, GATHER_SMEM>>>(
        objects, srel, rrel, relinfo, rb1, rb2, rb3, rb4);

    scatter_kernel<<<dim3(KSPLIT, BB), THREADS, SCATTER_SMEM>>>(rrel);

    final_kernel<<<BB * NN, 128>>>(objects, ow1, ob1, ow2, ob2, out);
}